// round 2
// baseline (speedup 1.0000x reference)
#include <cuda_runtime.h>
#include <cuda_bf16.h>
#include <cstdint>

// GraphSAGE 2-layer encoder.
// Restructure: (scatter_mean(h)[i] @ Wl) == inv_deg[i] * scatter_add(h @ Wl)[i]
// Per layer: t = h @ [Wl | Wr]   (dense dual GEMM, t row stride 128)
//            agg[dst] += t[src, 0:64]   (red.global.add.v4.f32)
//            out = 1/max(deg,1) * agg + b + t[:, 64:128]  (+ relu for layer 1)
// Degree counting is fused into the layer-1 scatter (c==0 lane adds 1.0).

#define MAXN 100000
#define MAXE 1600000

__device__ float g_t[MAXN * 128];      // [msg cols 0..63 | root cols 64..127]
__device__ float g_h[MAXN * 64];       // layer-1 output
__device__ float g_agg1[MAXN * 64];
__device__ float g_agg2[MAXN * 64];
__device__ float g_deg[MAXN];          // in-degree (fp32, exact for small ints)

// ---------------------------------------------------------------------------
// Zero accumulators + degree buffer (re-run on every graph replay)
// ---------------------------------------------------------------------------
__global__ void zero_kernel(int n) {
    const int total4 = n * 16;  // n*64 floats as float4
    const int stride = gridDim.x * blockDim.x;
    const float4 z = make_float4(0.f, 0.f, 0.f, 0.f);
    float4* a1 = reinterpret_cast<float4*>(g_agg1);
    float4* a2 = reinterpret_cast<float4*>(g_agg2);
    for (int i = blockIdx.x * blockDim.x + threadIdx.x; i < total4; i += stride) {
        a1[i] = z;
        a2[i] = z;
    }
    for (int i = blockIdx.x * blockDim.x + threadIdx.x; i < n; i += stride)
        g_deg[i] = 0.f;
}

// ---------------------------------------------------------------------------
// Dual GEMM: t[row, 0:128] = h[row, :] @ [Wl | Wr]
// 128 threads/block, one output column per thread, weights in registers,
// 4 rows per iteration staged through shared memory (broadcast reads).
// ---------------------------------------------------------------------------
__global__ void __launch_bounds__(128) gemm_dual_kernel(
    const float* __restrict__ x,
    const float* __restrict__ wl, const float* __restrict__ wr,
    int n, int layer)
{
    const float* __restrict__ h = (layer == 0) ? x : g_h;
    __shared__ float xs[4][64];
    const int col = threadIdx.x;  // 0..127

    float w[64];
#pragma unroll
    for (int k = 0; k < 64; k++)
        w[k] = (col < 64) ? __ldg(wl + k * 64 + col) : __ldg(wr + k * 64 + (col - 64));

    for (int row0 = blockIdx.x * 4; row0 < n; row0 += gridDim.x * 4) {
        __syncthreads();  // previous iteration's readers done with xs
#pragma unroll
        for (int i = 0; i < 2; i++) {
            int idx = threadIdx.x + i * 128;        // 0..255
            int rr = idx >> 6, k = idx & 63;
            int row = row0 + rr;
            xs[rr][k] = (row < n) ? __ldg(h + (size_t)row * 64 + k) : 0.f;
        }
        __syncthreads();

        float a0 = 0.f, a1 = 0.f, a2 = 0.f, a3 = 0.f;
#pragma unroll
        for (int k = 0; k < 64; k++) {
            float wk = w[k];
            a0 = fmaf(xs[0][k], wk, a0);
            a1 = fmaf(xs[1][k], wk, a1);
            a2 = fmaf(xs[2][k], wk, a2);
            a3 = fmaf(xs[3][k], wk, a3);
        }
        if (row0 + 0 < n) g_t[(size_t)(row0 + 0) * 128 + col] = a0;
        if (row0 + 1 < n) g_t[(size_t)(row0 + 1) * 128 + col] = a1;
        if (row0 + 2 < n) g_t[(size_t)(row0 + 2) * 128 + col] = a2;
        if (row0 + 3 < n) g_t[(size_t)(row0 + 3) * 128 + col] = a3;
    }
}

// ---------------------------------------------------------------------------
// Edge scatter: agg[dst, :] += t[src, 0:64].
// One work item = one float4 of one edge (16 items/edge). Consecutive threads
// share an edge -> src/dst loads broadcast, 256B gather fully coalesced.
// When count_deg, the c==0 lane also accumulates the in-degree.
// ---------------------------------------------------------------------------
__global__ void scatter_kernel(const int* __restrict__ src,
                               const int* __restrict__ dst,
                               int ne, int layer)
{
    float* __restrict__ agg = (layer == 0) ? g_agg1 : g_agg2;
    const int count_deg = (layer == 0);
    const long long total = (long long)ne * 16;
    const long long stride = (long long)gridDim.x * blockDim.x;
    for (long long it = (long long)blockIdx.x * blockDim.x + threadIdx.x;
         it < total; it += stride) {
        const int e = (int)(it >> 4);
        const int c = (int)(it & 15);
        const int s = __ldg(src + e);
        const int d = __ldg(dst + e);
        const float4 v = *reinterpret_cast<const float4*>(g_t + (size_t)s * 128 + c * 4);
        float* p = agg + (size_t)d * 64 + c * 4;
        asm volatile("red.global.add.v4.f32 [%0], {%1,%2,%3,%4};"
                     :: "l"(p), "f"(v.x), "f"(v.y), "f"(v.z), "f"(v.w) : "memory");
        if (count_deg && c == 0) {
            float* dp = &g_deg[d];
            asm volatile("red.global.add.f32 [%0], %1;" :: "l"(dp), "f"(1.0f) : "memory");
        }
    }
}

// ---------------------------------------------------------------------------
// Combine: out = 1/max(deg,1) * agg + bias + t[:, 64:128]  (optionally relu)
// ---------------------------------------------------------------------------
__global__ void combine_kernel(const float* __restrict__ bias,
                               float* __restrict__ out_ext,
                               int n, int layer)
{
    const float* __restrict__ agg = (layer == 0) ? g_agg1 : g_agg2;
    float* __restrict__ out = (layer == 0) ? g_h : out_ext;
    const int do_relu = (layer == 0);
    const int total = n * 16;
    const int stride = gridDim.x * blockDim.x;
    for (int it = blockIdx.x * blockDim.x + threadIdx.x; it < total; it += stride) {
        const int i = it >> 4;
        const int c = it & 15;
        const float iv = 1.0f / fmaxf(__ldg(g_deg + i), 1.0f);
        const float4 a = *reinterpret_cast<const float4*>(agg + (size_t)i * 64 + c * 4);
        const float4 r = *reinterpret_cast<const float4*>(g_t + (size_t)i * 128 + 64 + c * 4);
        const float4 b = *reinterpret_cast<const float4*>(bias + c * 4);
        float4 o;
        o.x = fmaf(iv, a.x, b.x + r.x);
        o.y = fmaf(iv, a.y, b.y + r.y);
        o.z = fmaf(iv, a.z, b.z + r.z);
        o.w = fmaf(iv, a.w, b.w + r.w);
        if (do_relu) {
            o.x = fmaxf(o.x, 0.f);
            o.y = fmaxf(o.y, 0.f);
            o.z = fmaxf(o.z, 0.f);
            o.w = fmaxf(o.w, 0.f);
        }
        *reinterpret_cast<float4*>(out + (size_t)i * 64 + c * 4) = o;
    }
}

// ---------------------------------------------------------------------------
// Launch.  Inputs (metadata order): x [N*64] f32, edge_index [2*E] i32,
//   w1l [64*64], b1l [64], w1r [64*64], w2l [64*64], b2l [64], w2r [64*64]
// Output: [N*64] f32
// ---------------------------------------------------------------------------
extern "C" void kernel_launch(void* const* d_in, const int* in_sizes, int n_in,
                              void* d_out, int out_size) {
    const float* x   = (const float*)d_in[0];
    const int*   ei  = (const int*)d_in[1];
    const float* w1l = (const float*)d_in[2];
    const float* b1l = (const float*)d_in[3];
    const float* w1r = (const float*)d_in[4];
    const float* w2l = (const float*)d_in[5];
    const float* b2l = (const float*)d_in[6];
    const float* w2r = (const float*)d_in[7];
    float* out = (float*)d_out;

    const int n  = in_sizes[0] / 64;
    const int ne = in_sizes[1] / 2;
    const int* src = ei;
    const int* dst = ei + ne;

    zero_kernel<<<2048, 256>>>(n);

    // Layer 1 (scatter also counts in-degree)
    gemm_dual_kernel<<<608, 128>>>(x, w1l, w1r, n, 0);
    scatter_kernel<<<4864, 256>>>(src, dst, ne, 0);
    combine_kernel<<<2048, 256>>>(b1l, out, n, 0);

    // Layer 2
    gemm_dual_kernel<<<608, 128>>>(x, w2l, w2r, n, 1);
    scatter_kernel<<<4864, 256>>>(src, dst, ne, 1);
    combine_kernel<<<2048, 256>>>(b2l, out, n, 1);
}

// round 4
// speedup vs baseline: 1.3101x; 1.3101x over previous
#include <cuda_runtime.h>
#include <cuda_bf16.h>
#include <cstdint>

// GraphSAGE 2-layer encoder — CSR pull formulation.
//
// (scatter_mean(h) @ Wl)[i] == inv_deg[i] * scatter_add(h @ Wl)[i], so per layer:
//   t = h @ [Wl | Wr]                        (dense dual GEMM, row stride 128)
//   out[i] = inv_deg[i]*sum_{e in CSR[i]} t[src_e,0:64] + b + t[i,64:128] (+relu)
// CSR built per launch: histogram -> block scan -> bin (deterministic work).
// No atomics on feature data: each node owns its reduction (pull, not push).

#define MAXN 100000
#define MAXE 1600000
#define SCAN_B 512

__device__ float g_t[MAXN * 128];       // [msg cols 0..63 | root cols 64..127]
__device__ float g_h[MAXN * 64];        // layer-1 output
__device__ int   g_rowptr[MAXN + 1];
__device__ int   g_cursor[MAXN];
__device__ int   g_ssrc[MAXE];          // src ids grouped by dst
__device__ int   g_degtmp[MAXN];        // histogram accumulator
__device__ int   g_scantmp[MAXN];       // per-block exclusive scan
__device__ int   g_bsums[SCAN_B];       // block sums (nb <= 196 for N=100K)

// ---------------------------------------------------------------------------
// CSR construction
// ---------------------------------------------------------------------------
__global__ void zero_deg_kernel(int n) {
    int i = blockIdx.x * blockDim.x + threadIdx.x;
    if (i < n) g_degtmp[i] = 0;
}

__global__ void hist_kernel(const int* __restrict__ dst, int ne) {
    const int stride = gridDim.x * blockDim.x;
    for (int e = blockIdx.x * blockDim.x + threadIdx.x; e < ne; e += stride)
        atomicAdd(&g_degtmp[__ldg(dst + e)], 1);
}

// Per-block exclusive scan of g_degtmp (SCAN_B elems/block) + block totals.
__global__ void __launch_bounds__(SCAN_B) scan1_kernel(int n) {
    __shared__ int sh[SCAN_B];
    const int tid = threadIdx.x;
    const int i = blockIdx.x * SCAN_B + tid;
    int v = (i < n) ? g_degtmp[i] : 0;
    sh[tid] = v;
    __syncthreads();
#pragma unroll
    for (int o = 1; o < SCAN_B; o <<= 1) {
        int t = (tid >= o) ? sh[tid - o] : 0;
        __syncthreads();
        sh[tid] += t;
        __syncthreads();
    }
    if (i < n) g_scantmp[i] = sh[tid] - v;          // exclusive
    if (tid == SCAN_B - 1) g_bsums[blockIdx.x] = sh[tid];
}

// Exclusive scan of block sums (single block).
__global__ void __launch_bounds__(SCAN_B) scan2_kernel(int nb) {
    __shared__ int sh[SCAN_B];
    const int tid = threadIdx.x;
    int v = (tid < nb) ? g_bsums[tid] : 0;
    sh[tid] = v;
    __syncthreads();
#pragma unroll
    for (int o = 1; o < SCAN_B; o <<= 1) {
        int t = (tid >= o) ? sh[tid - o] : 0;
        __syncthreads();
        sh[tid] += t;
        __syncthreads();
    }
    if (tid < nb) g_bsums[tid] = sh[tid] - v;       // exclusive
}

__global__ void scan3_kernel(int n, int ne) {
    int i = blockIdx.x * blockDim.x + threadIdx.x;
    if (i < n) {
        int rp = g_scantmp[i] + g_bsums[i / SCAN_B];
        g_rowptr[i] = rp;
        g_cursor[i] = rp;
    }
    if (i == 0) g_rowptr[n] = ne;
}

__global__ void bin_kernel(const int* __restrict__ src,
                           const int* __restrict__ dst, int ne) {
    const int stride = gridDim.x * blockDim.x;
    for (int e = blockIdx.x * blockDim.x + threadIdx.x; e < ne; e += stride) {
        int d = __ldg(dst + e);
        int pos = atomicAdd(&g_cursor[d], 1);
        g_ssrc[pos] = __ldg(src + e);
    }
}

// ---------------------------------------------------------------------------
// Dual GEMM: t[row, 0:128] = h[row, :] @ [Wl | Wr]   (proven at 311us total)
// ---------------------------------------------------------------------------
__global__ void __launch_bounds__(128) gemm_dual_kernel(
    const float* __restrict__ x,
    const float* __restrict__ wl, const float* __restrict__ wr,
    int n, int layer)
{
    const float* __restrict__ h = (layer == 0) ? x : g_h;
    __shared__ float xs[4][64];
    const int col = threadIdx.x;  // 0..127

    float w[64];
#pragma unroll
    for (int k = 0; k < 64; k++)
        w[k] = (col < 64) ? __ldg(wl + k * 64 + col) : __ldg(wr + k * 64 + (col - 64));

    for (int row0 = blockIdx.x * 4; row0 < n; row0 += gridDim.x * 4) {
        __syncthreads();
#pragma unroll
        for (int i = 0; i < 2; i++) {
            int idx = threadIdx.x + i * 128;
            int rr = idx >> 6, k = idx & 63;
            int row = row0 + rr;
            xs[rr][k] = (row < n) ? __ldg(h + (size_t)row * 64 + k) : 0.f;
        }
        __syncthreads();

        float a0 = 0.f, a1 = 0.f, a2 = 0.f, a3 = 0.f;
#pragma unroll
        for (int k = 0; k < 64; k++) {
            float wk = w[k];
            a0 = fmaf(xs[0][k], wk, a0);
            a1 = fmaf(xs[1][k], wk, a1);
            a2 = fmaf(xs[2][k], wk, a2);
            a3 = fmaf(xs[3][k], wk, a3);
        }
        if (row0 + 0 < n) g_t[(size_t)(row0 + 0) * 128 + col] = a0;
        if (row0 + 1 < n) g_t[(size_t)(row0 + 1) * 128 + col] = a1;
        if (row0 + 2 < n) g_t[(size_t)(row0 + 2) * 128 + col] = a2;
        if (row0 + 3 < n) g_t[(size_t)(row0 + 3) * 128 + col] = a3;
    }
}

// ---------------------------------------------------------------------------
// CSR reduce + fused epilogue. One warp per node; lane owns cols [2l, 2l+1].
// out[i] = (1/max(deg,1)) * sum_e t[ssrc[e], 0:64] + bias + t[i, 64:128]
// Unroll-8 gather: ~8 outstanding LDG.64/lane to cover L2 latency (~250cyc).
// ---------------------------------------------------------------------------
__global__ void __launch_bounds__(256) csr_reduce_kernel(
    const float* __restrict__ bias, float* __restrict__ out_ext,
    int n, int layer)
{
    float* __restrict__ out = (layer == 0) ? g_h : out_ext;
    const int do_relu = (layer == 0);
    const int warp = (blockIdx.x * blockDim.x + threadIdx.x) >> 5;
    const int lane = threadIdx.x & 31;
    if (warp >= n) return;
    const int i = warp;

    const int beg = __ldg(g_rowptr + i);
    const int end = __ldg(g_rowptr + i + 1);
    const int c2 = lane * 2;

    float ax = 0.f, ay = 0.f;
    int e = beg;
    for (; e + 8 <= end; e += 8) {
        int s[8];
#pragma unroll
        for (int j = 0; j < 8; j++) s[j] = __ldg(g_ssrc + e + j);
        float2 v[8];
#pragma unroll
        for (int j = 0; j < 8; j++)
            v[j] = *reinterpret_cast<const float2*>(g_t + (size_t)s[j] * 128 + c2);
#pragma unroll
        for (int j = 0; j < 8; j++) {
            ax += v[j].x;
            ay += v[j].y;
        }
    }
    for (; e < end; e++) {
        const int s = __ldg(g_ssrc + e);
        const float2 v = *reinterpret_cast<const float2*>(g_t + (size_t)s * 128 + c2);
        ax += v.x;
        ay += v.y;
    }

    const float inv = 1.0f / fmaxf((float)(end - beg), 1.0f);
    const float2 r = *reinterpret_cast<const float2*>(g_t + (size_t)i * 128 + 64 + c2);
    const float2 b = *reinterpret_cast<const float2*>(bias + c2);
    float ox = fmaf(inv, ax, b.x + r.x);
    float oy = fmaf(inv, ay, b.y + r.y);
    if (do_relu) {
        ox = fmaxf(ox, 0.f);
        oy = fmaxf(oy, 0.f);
    }
    *reinterpret_cast<float2*>(out + (size_t)i * 64 + c2) = make_float2(ox, oy);
}

// ---------------------------------------------------------------------------
// Launch.  Inputs: x [N*64] f32, edge_index [2*E] i32, w1l, b1l, w1r, w2l, b2l, w2r
// Output: [N*64] f32
// ---------------------------------------------------------------------------
extern "C" void kernel_launch(void* const* d_in, const int* in_sizes, int n_in,
                              void* d_out, int out_size) {
    const float* x   = (const float*)d_in[0];
    const int*   ei  = (const int*)d_in[1];
    const float* w1l = (const float*)d_in[2];
    const float* b1l = (const float*)d_in[3];
    const float* w1r = (const float*)d_in[4];
    const float* w2l = (const float*)d_in[5];
    const float* b2l = (const float*)d_in[6];
    const float* w2r = (const float*)d_in[7];
    float* out = (float*)d_out;

    const int n  = in_sizes[0] / 64;
    const int ne = in_sizes[1] / 2;
    const int* src = ei;
    const int* dst = ei + ne;

    const int nb = (n + SCAN_B - 1) / SCAN_B;

    // CSR build
    zero_deg_kernel<<<(n + 255) / 256, 256>>>(n);
    hist_kernel<<<1216, 256>>>(dst, ne);
    scan1_kernel<<<nb, SCAN_B>>>(n);
    scan2_kernel<<<1, SCAN_B>>>(nb);
    scan3_kernel<<<(n + 255) / 256, 256>>>(n, ne);
    bin_kernel<<<1216, 256>>>(src, dst, ne);

    const int rblocks = (n * 32 + 255) / 256;  // one warp per node

    // Layer 1
    gemm_dual_kernel<<<608, 128>>>(x, w1l, w1r, n, 0);
    csr_reduce_kernel<<<rblocks, 256>>>(b1l, out, n, 0);

    // Layer 2
    gemm_dual_kernel<<<608, 128>>>(x, w2l, w2r, n, 1);
    csr_reduce_kernel<<<rblocks, 256>>>(b2l, out, n, 1);
}

// round 9
// speedup vs baseline: 1.3553x; 1.0345x over previous
#include <cuda_runtime.h>
#include <cuda_bf16.h>
#include <cstdint>

// GraphSAGE 2-layer encoder — CSR pull + packed-f32x2 GEMM.
//
// Per layer: t = h @ [Wl | Wr]  (dense dual GEMM, row stride 128)
//            out[i] = inv_deg[i]*sum_{e in CSR[i]} t[src_e,0:64] + b + t[i,64:128] (+relu)
// CSR built per launch (histogram -> scan -> bin). Pull: no feature atomics.

#define MAXN 100000
#define MAXE 1600000
#define SCAN_B 512

__device__ float g_t[MAXN * 128];       // [msg cols 0..63 | root cols 64..127]
__device__ float g_h[MAXN * 64];        // layer-1 output
__device__ int   g_rowptr[MAXN + 1];
__device__ int   g_cursor[MAXN];
__device__ int   g_ssrc[MAXE];          // src ids grouped by dst
__device__ int   g_degtmp[MAXN];        // histogram accumulator
__device__ int   g_scantmp[MAXN];       // per-block exclusive scan
__device__ int   g_bsums[SCAN_B];       // block sums (nb <= 196 for N=100K)

// ---- packed fp32x2 helpers (FFMA2: 2x fp32 FMA throughput, exact) ---------
__device__ __forceinline__ unsigned long long pack2(float x, float y) {
    unsigned long long r;
    asm("mov.b64 %0, {%1, %2};" : "=l"(r) : "f"(x), "f"(y));
    return r;
}
__device__ __forceinline__ void fma2(unsigned long long& acc,
                                     unsigned long long a, unsigned long long b) {
    asm("fma.rn.f32x2 %0, %1, %2, %0;" : "+l"(acc) : "l"(a), "l"(b));
}
__device__ __forceinline__ void unpack2(unsigned long long v, float& x, float& y) {
    asm("mov.b64 {%0, %1}, %2;" : "=f"(x), "=f"(y) : "l"(v));
}

// ---------------------------------------------------------------------------
// CSR construction
// ---------------------------------------------------------------------------
__global__ void zero_deg_kernel(int n) {
    int i = blockIdx.x * blockDim.x + threadIdx.x;
    if (i < n) g_degtmp[i] = 0;
}

__global__ void hist_kernel(const int* __restrict__ dst, int ne) {
    const int stride = gridDim.x * blockDim.x;
    for (int e = blockIdx.x * blockDim.x + threadIdx.x; e < ne; e += stride)
        atomicAdd(&g_degtmp[__ldg(dst + e)], 1);
}

// Per-block exclusive scan of g_degtmp (SCAN_B elems/block) + block totals.
__global__ void __launch_bounds__(SCAN_B) scan1_kernel(int n) {
    __shared__ int sh[SCAN_B];
    const int tid = threadIdx.x;
    const int i = blockIdx.x * SCAN_B + tid;
    int v = (i < n) ? g_degtmp[i] : 0;
    sh[tid] = v;
    __syncthreads();
#pragma unroll
    for (int o = 1; o < SCAN_B; o <<= 1) {
        int t = (tid >= o) ? sh[tid - o] : 0;
        __syncthreads();
        sh[tid] += t;
        __syncthreads();
    }
    if (i < n) g_scantmp[i] = sh[tid] - v;          // exclusive
    if (tid == SCAN_B - 1) g_bsums[blockIdx.x] = sh[tid];
}

// Fused: each block scans g_bsums (nb <= 256) in smem, then writes rowptr.
__global__ void __launch_bounds__(256) scan3_kernel(int n, int ne, int nb) {
    __shared__ int sb[256];
    __shared__ int se[256];
    const int tid = threadIdx.x;
    int v = (tid < nb) ? g_bsums[tid] : 0;
    sb[tid] = v;
    __syncthreads();
#pragma unroll
    for (int o = 1; o < 256; o <<= 1) {
        int t = (tid >= o) ? sb[tid - o] : 0;
        __syncthreads();
        sb[tid] += t;
        __syncthreads();
    }
    se[tid] = sb[tid] - v;                          // exclusive block offset
    __syncthreads();

    const int i = blockIdx.x * blockDim.x + tid;
    if (i < n) {
        int rp = g_scantmp[i] + se[i / SCAN_B];
        g_rowptr[i] = rp;
        g_cursor[i] = rp;
    }
    if (i == 0) g_rowptr[n] = ne;
}

__global__ void bin_kernel(const int* __restrict__ src,
                           const int* __restrict__ dst, int ne) {
    const int stride = gridDim.x * blockDim.x;
    for (int e = blockIdx.x * blockDim.x + threadIdx.x; e < ne; e += stride) {
        int d = __ldg(dst + e);
        int pos = atomicAdd(&g_cursor[d], 1);
        g_ssrc[pos] = __ldg(src + e);
    }
}

// ---------------------------------------------------------------------------
// Dual GEMM: t[row, 0:128] = h[row, :] @ [Wl | Wr]
// 128 threads/block, one output column/thread, weights in registers.
// 8 rows/iter; row pairs interleaved in smem (pair p, k) = {row2p[k], row2p+1[k]}
// so the inner loop per k is 4x LDS.64 (broadcast) + 1 pack + 4 FFMA2 -> 8 rows.
// ---------------------------------------------------------------------------
__global__ void __launch_bounds__(128) gemm_dual_kernel(
    const float* __restrict__ x,
    const float* __restrict__ wl, const float* __restrict__ wr,
    int n, int layer)
{
    const float* __restrict__ h = (layer == 0) ? x : g_h;
    __shared__ float xs[4 * 64 * 2];   // pair-major: xs[p*128 + k*2 + half]
    const int col = threadIdx.x;       // 0..127

    float w[64];
#pragma unroll
    for (int k = 0; k < 64; k++)
        w[k] = (col < 64) ? __ldg(wl + k * 64 + col) : __ldg(wr + k * 64 + (col - 64));

    for (int row0 = blockIdx.x * 8; row0 < n; row0 += gridDim.x * 8) {
        __syncthreads();  // previous iteration's readers done with xs
#pragma unroll
        for (int i = 0; i < 4; i++) {
            int idx = threadIdx.x + i * 128;        // 0..511
            int rr = idx >> 6, k = idx & 63;        // rr: 0..7
            int row = row0 + rr;
            float val = (row < n) ? __ldg(h + (size_t)row * 64 + k) : 0.f;
            xs[(rr >> 1) * 128 + k * 2 + (rr & 1)] = val;
        }
        __syncthreads();

        unsigned long long a0 = 0ull, a1 = 0ull, a2 = 0ull, a3 = 0ull;
        const unsigned long long* xp = reinterpret_cast<const unsigned long long*>(xs);
#pragma unroll
        for (int k = 0; k < 64; k++) {
            const unsigned long long wkk = pack2(w[k], w[k]);
            fma2(a0, xp[k], wkk);
            fma2(a1, xp[64 + k], wkk);
            fma2(a2, xp[128 + k], wkk);
            fma2(a3, xp[192 + k], wkk);
        }

        float r[8];
        unpack2(a0, r[0], r[1]);
        unpack2(a1, r[2], r[3]);
        unpack2(a2, r[4], r[5]);
        unpack2(a3, r[6], r[7]);
#pragma unroll
        for (int j = 0; j < 8; j++)
            if (row0 + j < n) g_t[(size_t)(row0 + j) * 128 + col] = r[j];
    }
}

// ---------------------------------------------------------------------------
// CSR reduce + fused epilogue. One warp per node; lane owns cols [2l, 2l+1].
// Unroll-8 gather: ~8 outstanding LDG.64/lane to cover L2 latency (~250cyc).
// ---------------------------------------------------------------------------
__global__ void __launch_bounds__(256) csr_reduce_kernel(
    const float* __restrict__ bias, float* __restrict__ out_ext,
    int n, int layer)
{
    float* __restrict__ out = (layer == 0) ? g_h : out_ext;
    const int do_relu = (layer == 0);
    const int warp = (blockIdx.x * blockDim.x + threadIdx.x) >> 5;
    const int lane = threadIdx.x & 31;
    if (warp >= n) return;
    const int i = warp;

    const int beg = __ldg(g_rowptr + i);
    const int end = __ldg(g_rowptr + i + 1);
    const int c2 = lane * 2;

    float ax = 0.f, ay = 0.f;
    int e = beg;
    for (; e + 8 <= end; e += 8) {
        int s[8];
#pragma unroll
        for (int j = 0; j < 8; j++) s[j] = __ldg(g_ssrc + e + j);
        float2 v[8];
#pragma unroll
        for (int j = 0; j < 8; j++)
            v[j] = *reinterpret_cast<const float2*>(g_t + (size_t)s[j] * 128 + c2);
#pragma unroll
        for (int j = 0; j < 8; j++) {
            ax += v[j].x;
            ay += v[j].y;
        }
    }
    for (; e < end; e++) {
        const int s = __ldg(g_ssrc + e);
        const float2 v = *reinterpret_cast<const float2*>(g_t + (size_t)s * 128 + c2);
        ax += v.x;
        ay += v.y;
    }

    const float inv = 1.0f / fmaxf((float)(end - beg), 1.0f);
    const float2 r = *reinterpret_cast<const float2*>(g_t + (size_t)i * 128 + 64 + c2);
    const float2 b = *reinterpret_cast<const float2*>(bias + c2);
    float ox = fmaf(inv, ax, b.x + r.x);
    float oy = fmaf(inv, ay, b.y + r.y);
    if (do_relu) {
        ox = fmaxf(ox, 0.f);
        oy = fmaxf(oy, 0.f);
    }
    *reinterpret_cast<float2*>(out + (size_t)i * 64 + c2) = make_float2(ox, oy);
}

// ---------------------------------------------------------------------------
// Launch.  Inputs: x [N*64] f32, edge_index [2*E] i32, w1l, b1l, w1r, w2l, b2l, w2r
// Output: [N*64] f32
// ---------------------------------------------------------------------------
extern "C" void kernel_launch(void* const* d_in, const int* in_sizes, int n_in,
                              void* d_out, int out_size) {
    const float* x   = (const float*)d_in[0];
    const int*   ei  = (const int*)d_in[1];
    const float* w1l = (const float*)d_in[2];
    const float* b1l = (const float*)d_in[3];
    const float* w1r = (const float*)d_in[4];
    const float* w2l = (const float*)d_in[5];
    const float* b2l = (const float*)d_in[6];
    const float* w2r = (const float*)d_in[7];
    float* out = (float*)d_out;

    const int n  = in_sizes[0] / 64;
    const int ne = in_sizes[1] / 2;
    const int* src = ei;
    const int* dst = ei + ne;

    const int nb = (n + SCAN_B - 1) / SCAN_B;   // <= 196 for N=100K

    // CSR build
    zero_deg_kernel<<<(n + 255) / 256, 256>>>(n);
    hist_kernel<<<1216, 256>>>(dst, ne);
    scan1_kernel<<<nb, SCAN_B>>>(n);
    scan3_kernel<<<(n + 255) / 256, 256>>>(n, ne, nb);
    bin_kernel<<<1216, 256>>>(src, dst, ne);

    const int rblocks = (n * 32 + 255) / 256;  // one warp per node

    // Layer 1
    gemm_dual_kernel<<<608, 128>>>(x, w1l, w1r, n, 0);
    csr_reduce_kernel<<<rblocks, 256>>>(b1l, out, n, 0);

    // Layer 2
    gemm_dual_kernel<<<608, 128>>>(x, w2l, w2r, n, 1);
    csr_reduce_kernel<<<rblocks, 256>>>(b2l, out, n, 1);
}